// round 1
// baseline (speedup 1.0000x reference)
#include <cuda_runtime.h>
#include <math.h>

#define Nn 50000
#define Ee 800000
#define Rr 64
#define Dd 64
#define Ll 4
#define Bb 2
#define Kk 32

// scratch (no allocations allowed)
__device__ float g_x[Bb * Nn * Dd];    // 25.6 MB
__device__ float g_agg[Bb * Nn * Dd];  // 25.6 MB

// out = boundary_extra + query added at h_index   (to_agg selects target buffer)
__global__ void k_init(const float* __restrict__ be, const float* __restrict__ rel,
                       const int* __restrict__ h_index, const int* __restrict__ r_index,
                       int to_agg) {
    int idx = blockIdx.x * blockDim.x + threadIdx.x;
    if (idx >= Bb * Nn * Dd) return;
    int d = idx & (Dd - 1);
    int bn = idx >> 6;
    int b = bn / Nn;
    int n = bn - b * Nn;
    float v = be[idx];
    if (n == h_index[b]) v += rel[(b * Rr + r_index[b]) * Dd + d];
    if (to_agg) g_agg[idx] = v;
    else        g_x[idx]   = v;
}

// agg[b,dst,:] += x[b,src,:] * rel[b,et,:]
__global__ void k_scatter(const int* __restrict__ ei, const int* __restrict__ et,
                          const float* __restrict__ rel) {
    int idx = blockIdx.x * blockDim.x + threadIdx.x;
    if (idx >= Ee * Bb * Dd) return;        // 102,400,000 < 2^31
    int d = idx & 63;
    int t = idx >> 6;
    int b = t & 1;
    int e = t >> 1;
    int src = ei[e];
    int dst = ei[Ee + e];
    int r   = et[e];
    float v = g_x[(b * Nn + src) * Dd + d] * rel[(b * Rr + r) * Dd + d];
    atomicAdd(&g_agg[(b * Nn + dst) * Dd + d], v);
}

// per row: out = relu(LN(concat(x,agg) @ W + b)); x = out + x
// one warp per row, lane computes outputs {lane, lane+32} (conflict-free smem W reads)
__global__ void k_dense(const float* __restrict__ W, const float* __restrict__ bias,
                        const float* __restrict__ gam, const float* __restrict__ bet) {
    __shared__ float sW[2 * Dd * Dd];   // [j][d], 32 KB
    __shared__ float sb[Dd], sg[Dd], sbe[Dd];
    __shared__ float sIn[8][2 * Dd];

    int tid = threadIdx.x;
    for (int i = tid; i < 2 * Dd * Dd; i += blockDim.x) sW[i] = W[i];
    if (tid < Dd) { sb[tid] = bias[tid]; sg[tid] = gam[tid]; sbe[tid] = bet[tid]; }
    __syncthreads();

    int w = tid >> 5, lane = tid & 31;
    int row = blockIdx.x * 8 + w;
    if (row >= Bb * Nn) return;

    const float* xr = g_x   + (size_t)row * Dd;
    const float* ar = g_agg + (size_t)row * Dd;
    float x0 = xr[lane], x1 = xr[lane + 32];
    sIn[w][lane]      = x0;
    sIn[w][lane + 32] = x1;
    sIn[w][64 + lane]      = ar[lane];
    sIn[w][96 + lane]      = ar[lane + 32];
    __syncwarp();

    float acc0 = sb[lane], acc1 = sb[lane + 32];
    #pragma unroll
    for (int j = 0; j < 2 * Dd; j++) {
        float in = sIn[w][j];
        acc0 += in * sW[j * Dd + lane];
        acc1 += in * sW[j * Dd + lane + 32];
    }

    // layernorm over the 64 outputs (2 per lane)
    float s = acc0 + acc1;
    #pragma unroll
    for (int o = 16; o > 0; o >>= 1) s += __shfl_xor_sync(0xffffffffu, s, o);
    float mu = s * (1.0f / 64.0f);
    float c0 = acc0 - mu, c1 = acc1 - mu;
    float q = c0 * c0 + c1 * c1;
    #pragma unroll
    for (int o = 16; o > 0; o >>= 1) q += __shfl_xor_sync(0xffffffffu, q, o);
    float inv = rsqrtf(q * (1.0f / 64.0f) + 1e-5f);

    float v0 = fmaxf(c0 * inv * sg[lane] + sbe[lane], 0.0f);
    float v1 = fmaxf(c1 * inv * sg[lane + 32] + sbe[lane + 32], 0.0f);

    float* xw = g_x + (size_t)row * Dd;
    xw[lane]      = v0 + x0;
    xw[lane + 32] = v1 + x1;
}

// score[b,k] = relu(concat(x[b,t], query[b]) @ w1 + b1) . w2 + b2
__global__ void k_out(const int* __restrict__ t_index, const int* __restrict__ r_index,
                      const float* __restrict__ rel,
                      const float* __restrict__ w1, const float* __restrict__ b1,
                      const float* __restrict__ w2, const float* __restrict__ b2,
                      float* __restrict__ out) {
    __shared__ float feat[2 * Dd];
    __shared__ float red[64];
    int b = blockIdx.x >> 5;   // Kk == 32
    int k = blockIdx.x & 31;
    int tid = threadIdx.x;     // 0..63
    int t = t_index[b * Kk + k];
    feat[tid]      = g_x[((size_t)(b * Nn + t)) * Dd + tid];
    feat[Dd + tid] = rel[(b * Rr + r_index[b]) * Dd + tid];
    __syncthreads();
    float h = b1[tid];
    #pragma unroll
    for (int j = 0; j < 2 * Dd; j++) h += feat[j] * w1[j * Dd + tid];
    h = fmaxf(h, 0.0f);
    red[tid] = h * w2[tid];
    __syncthreads();
    if (tid < 32) {
        float v = red[tid] + red[tid + 32];
        #pragma unroll
        for (int o = 16; o > 0; o >>= 1) v += __shfl_xor_sync(0xffffffffu, v, o);
        if (tid == 0) out[blockIdx.x] = v + b2[0];
    }
}

extern "C" void kernel_launch(void* const* d_in, const int* in_sizes, int n_in,
                              void* d_out, int out_size) {
    const int*   edge_index = (const int*)d_in[0];
    const int*   edge_type  = (const int*)d_in[1];
    const int*   h_index    = (const int*)d_in[2];
    const int*   r_index    = (const int*)d_in[3];
    const int*   t_index    = (const int*)d_in[4];
    const float* rel        = (const float*)d_in[5];
    const float* be         = (const float*)d_in[6];
    const float* lW         = (const float*)d_in[7];
    const float* lb         = (const float*)d_in[8];
    const float* lng        = (const float*)d_in[9];
    const float* lnb        = (const float*)d_in[10];
    const float* w1         = (const float*)d_in[11];
    const float* b1         = (const float*)d_in[12];
    const float* w2         = (const float*)d_in[13];
    const float* b2         = (const float*)d_in[14];
    float* out = (float*)d_out;

    const int bnd = Bb * Nn * Dd;
    const int init_blocks = (bnd + 255) / 256;
    const int scat_threads = Ee * Bb * Dd;          // 102.4M
    const int scat_blocks  = (scat_threads + 255) / 256;
    const int dense_blocks = (Bb * Nn + 7) / 8;     // 12500

    // x = boundary
    k_init<<<init_blocks, 256>>>(be, rel, h_index, r_index, /*to_agg=*/0);

    for (int l = 0; l < Ll; l++) {
        // agg = boundary
        k_init<<<init_blocks, 256>>>(be, rel, h_index, r_index, /*to_agg=*/1);
        // agg += segment_sum(x[src] * rel[edge_type])
        k_scatter<<<scat_blocks, 256>>>(edge_index, edge_type, rel);
        // x = relu(LN(concat(x,agg)@W + b)) + x
        k_dense<<<dense_blocks, 256>>>(lW + l * 2 * Dd * Dd, lb + l * Dd,
                                       lng + l * Dd, lnb + l * Dd);
    }

    k_out<<<Bb * Kk, 64>>>(t_index, r_index, rel, w1, b1, w2, b2, out);
}

// round 2
// speedup vs baseline: 2.5870x; 2.5870x over previous
#include <cuda_runtime.h>
#include <math.h>

#define Nn 50000
#define Ee 800000
#define Rr 64
#define Dd 64
#define Ll 4
#define Bb 2
#define Kk 32

// scratch (no allocations allowed)
__device__ float g_x[Bb * Nn * Dd];    // 25.6 MB
__device__ float g_agg[Bb * Nn * Dd];  // 25.6 MB

// out = boundary_extra + query added at h_index   (to_agg selects target buffer)
__global__ void k_init(const float* __restrict__ be, const float* __restrict__ rel,
                       const int* __restrict__ h_index, const int* __restrict__ r_index,
                       int to_agg) {
    int idx = blockIdx.x * blockDim.x + threadIdx.x;
    if (idx >= Bb * Nn * Dd) return;
    int d = idx & (Dd - 1);
    int bn = idx >> 6;
    int b = bn / Nn;
    int n = bn - b * Nn;
    float v = be[idx];
    if (n == h_index[b]) v += rel[(b * Rr + r_index[b]) * Dd + d];
    if (to_agg) g_agg[idx] = v;
    else        g_x[idx]   = v;
}

// agg[b,dst,:] += x[b,src,:] * rel[b,et,:]   — one thread per float4
__global__ void k_scatter(const int* __restrict__ ei, const int* __restrict__ et,
                          const float* __restrict__ rel) {
    int idx = blockIdx.x * blockDim.x + threadIdx.x;
    if (idx >= Ee * Bb * 16) return;        // 25.6M
    int d4 = idx & 15;          // float4 index within D=64
    int t  = idx >> 4;
    int b  = t & 1;
    int e  = t >> 1;
    int src = ei[e];
    int dst = ei[Ee + e];
    int r   = et[e];
    const float4 xv = *reinterpret_cast<const float4*>(&g_x[((b * Nn + src) << 6) + (d4 << 2)]);
    const float4 rv = *reinterpret_cast<const float4*>(&rel[((b * Rr + r) << 6) + (d4 << 2)]);
    float v0 = xv.x * rv.x, v1 = xv.y * rv.y, v2 = xv.z * rv.z, v3 = xv.w * rv.w;
    float* dp = &g_agg[((b * Nn + dst) << 6) + (d4 << 2)];
    asm volatile("red.global.add.v4.f32 [%0], {%1, %2, %3, %4};"
                 :: "l"(dp), "f"(v0), "f"(v1), "f"(v2), "f"(v3) : "memory");
}

// per row: out = relu(LN(concat(x,agg) @ W + b)); x = out + x
// 64 rows/block, 8 rows per warp register-blocked, lane computes outputs {2*lane, 2*lane+1}
__global__ void k_dense(const float* __restrict__ W, const float* __restrict__ bias,
                        const float* __restrict__ gam, const float* __restrict__ bet) {
    extern __shared__ float smem[];
    float* sW  = smem;              // [128][64]  32 KB
    float* sIn = smem + 128 * Dd;   // [64][128]  32 KB

    const int tid  = threadIdx.x;
    const int w    = tid >> 5;
    const int lane = tid & 31;
    const int base = blockIdx.x * 64;

    // load W (8192 floats) as float4, 8 per thread
    {
        const float4* Wv = reinterpret_cast<const float4*>(W);
        float4* sWv = reinterpret_cast<float4*>(sW);
        #pragma unroll
        for (int k = 0; k < 8; k++) sWv[tid + k * 256] = Wv[tid + k * 256];
    }
    // load inputs: 64 rows x 128 floats = 2048 float4 slots; slot = r*32 + c4
    {
        float4* sInv = reinterpret_cast<float4*>(sIn);
        #pragma unroll
        for (int k = 0; k < 8; k++) {
            int pos = tid + k * 256;
            int r   = pos >> 5;
            int c4  = pos & 31;
            int row = base + r;
            float4 v = make_float4(0.f, 0.f, 0.f, 0.f);
            if (row < Bb * Nn) {
                if (c4 < 16)
                    v = *reinterpret_cast<const float4*>(&g_x[((size_t)row << 6) + (c4 << 2)]);
                else
                    v = *reinterpret_cast<const float4*>(&g_agg[((size_t)row << 6) + ((c4 - 16) << 2)]);
            }
            sInv[pos] = v;
        }
    }
    __syncthreads();

    const int r0 = w * 8;   // first local row for this warp
    float2 bv = *reinterpret_cast<const float2*>(&bias[2 * lane]);
    float ax[8], ay[8];
    #pragma unroll
    for (int i = 0; i < 8; i++) { ax[i] = bv.x; ay[i] = bv.y; }

    #pragma unroll 8
    for (int j2 = 0; j2 < 64; j2++) {
        float2 w0 = *reinterpret_cast<const float2*>(&sW[(2 * j2) * Dd + 2 * lane]);
        float2 w1 = *reinterpret_cast<const float2*>(&sW[(2 * j2 + 1) * Dd + 2 * lane]);
        #pragma unroll
        for (int i = 0; i < 8; i++) {
            float2 in = *reinterpret_cast<const float2*>(&sIn[(r0 + i) * 128 + 2 * j2]);
            ax[i] += in.x * w0.x + in.y * w1.x;
            ay[i] += in.x * w0.y + in.y * w1.y;
        }
    }

    float2 gv = *reinterpret_cast<const float2*>(&gam[2 * lane]);
    float2 tv = *reinterpret_cast<const float2*>(&bet[2 * lane]);

    #pragma unroll
    for (int i = 0; i < 8; i++) {
        int row = base + r0 + i;
        if (row >= Bb * Nn) break;   // uniform across warp
        float s = ax[i] + ay[i];
        #pragma unroll
        for (int o = 16; o > 0; o >>= 1) s += __shfl_xor_sync(0xffffffffu, s, o);
        float mu = s * (1.0f / 64.0f);
        float c0 = ax[i] - mu, c1 = ay[i] - mu;
        float q = c0 * c0 + c1 * c1;
        #pragma unroll
        for (int o = 16; o > 0; o >>= 1) q += __shfl_xor_sync(0xffffffffu, q, o);
        float inv = rsqrtf(q * (1.0f / 64.0f) + 1e-5f);
        float2 xr = *reinterpret_cast<const float2*>(&sIn[(r0 + i) * 128 + 2 * lane]);
        float v0 = fmaxf(c0 * inv * gv.x + tv.x, 0.0f) + xr.x;
        float v1 = fmaxf(c1 * inv * gv.y + tv.y, 0.0f) + xr.y;
        *reinterpret_cast<float2*>(&g_x[((size_t)row << 6) + 2 * lane]) = make_float2(v0, v1);
    }
}

// score[b,k] = relu(concat(x[b,t], query[b]) @ w1 + b1) . w2 + b2
__global__ void k_out(const int* __restrict__ t_index, const int* __restrict__ r_index,
                      const float* __restrict__ rel,
                      const float* __restrict__ w1, const float* __restrict__ b1,
                      const float* __restrict__ w2, const float* __restrict__ b2,
                      float* __restrict__ out) {
    __shared__ float feat[2 * Dd];
    __shared__ float red[64];
    int b = blockIdx.x >> 5;   // Kk == 32
    int k = blockIdx.x & 31;
    int tid = threadIdx.x;     // 0..63
    int t = t_index[b * Kk + k];
    feat[tid]      = g_x[((size_t)(b * Nn + t)) * Dd + tid];
    feat[Dd + tid] = rel[(b * Rr + r_index[b]) * Dd + tid];
    __syncthreads();
    float h = b1[tid];
    #pragma unroll
    for (int j = 0; j < 2 * Dd; j++) h += feat[j] * w1[j * Dd + tid];
    h = fmaxf(h, 0.0f);
    red[tid] = h * w2[tid];
    __syncthreads();
    if (tid < 32) {
        float v = red[tid] + red[tid + 32];
        #pragma unroll
        for (int o = 16; o > 0; o >>= 1) v += __shfl_xor_sync(0xffffffffu, v, o);
        if (tid == 0) out[blockIdx.x] = v + b2[0];
    }
}

extern "C" void kernel_launch(void* const* d_in, const int* in_sizes, int n_in,
                              void* d_out, int out_size) {
    const int*   edge_index = (const int*)d_in[0];
    const int*   edge_type  = (const int*)d_in[1];
    const int*   h_index    = (const int*)d_in[2];
    const int*   r_index    = (const int*)d_in[3];
    const int*   t_index    = (const int*)d_in[4];
    const float* rel        = (const float*)d_in[5];
    const float* be         = (const float*)d_in[6];
    const float* lW         = (const float*)d_in[7];
    const float* lb         = (const float*)d_in[8];
    const float* lng        = (const float*)d_in[9];
    const float* lnb        = (const float*)d_in[10];
    const float* w1         = (const float*)d_in[11];
    const float* b1         = (const float*)d_in[12];
    const float* w2         = (const float*)d_in[13];
    const float* b2         = (const float*)d_in[14];
    float* out = (float*)d_out;

    const int bnd = Bb * Nn * Dd;
    const int init_blocks = (bnd + 255) / 256;
    const int scat_threads = Ee * Bb * 16;          // 25.6M (float4 granularity)
    const int scat_blocks  = (scat_threads + 255) / 256;
    const int dense_blocks = (Bb * Nn + 63) / 64;   // 1563
    const int dense_smem   = 2 * 128 * Dd * sizeof(float);  // 64 KB

    static int attr_set = 0;
    if (!attr_set) {
        cudaFuncSetAttribute(k_dense, cudaFuncAttributeMaxDynamicSharedMemorySize, dense_smem);
        attr_set = 1;
    }

    // x = boundary
    k_init<<<init_blocks, 256>>>(be, rel, h_index, r_index, /*to_agg=*/0);

    for (int l = 0; l < Ll; l++) {
        // agg = boundary
        k_init<<<init_blocks, 256>>>(be, rel, h_index, r_index, /*to_agg=*/1);
        // agg += segment_sum(x[src] * rel[edge_type])
        k_scatter<<<scat_blocks, 256>>>(edge_index, edge_type, rel);
        // x = relu(LN(concat(x,agg)@W + b)) + x
        k_dense<<<dense_blocks, 256, dense_smem>>>(lW + l * 2 * Dd * Dd, lb + l * Dd,
                                                   lng + l * Dd, lnb + l * Dd);
    }

    k_out<<<Bb * Kk, 64>>>(t_index, r_index, rel, w1, b1, w2, b2, out);
}

// round 3
// speedup vs baseline: 3.3756x; 1.3048x over previous
#include <cuda_runtime.h>
#include <math.h>

#define Nn 50000
#define Ee 800000
#define Rr 64
#define Dd 64
#define Ll 4
#define Bb 2
#define Kk 32

// scratch (no allocations allowed)
__device__ float g_x[Bb * Nn * Dd];    // 25.6 MB
__device__ float g_agg[Bb * Nn * Dd];  // 25.6 MB
__device__ int   g_deg[Nn + 1];        // histogram -> rowptr (in place)
__device__ int   g_cursor[Nn];
__device__ int2  g_epack[Ee];          // (src, edge_type) sorted by dst

#define FMA2(d, a, b, c) asm("fma.rn.f32x2 %0, %1, %2, %3;" : "=l"(d) : "l"(a), "l"(b), "l"(c))

// ---------------- CSR build ----------------
__global__ void k_zero() {
    int i = blockIdx.x * blockDim.x + threadIdx.x;
    if (i <= Nn) g_deg[i] = 0;
    if (i < Nn)  g_cursor[i] = 0;
}

__global__ void k_hist(const int* __restrict__ ei) {
    int e = blockIdx.x * blockDim.x + threadIdx.x;
    if (e < Ee) atomicAdd(&g_deg[ei[Ee + e] + 1], 1);
}

// single-block inclusive scan over g_deg[0..Nn]
__global__ void k_scan() {
    __shared__ int s[1024];
    __shared__ int carry_s;
    int t = threadIdx.x;
    if (t == 0) carry_s = 0;
    __syncthreads();
    for (int base = 0; base <= Nn; base += 1024) {
        int i = base + t;
        int v = (i <= Nn) ? g_deg[i] : 0;
        s[t] = v;
        __syncthreads();
        #pragma unroll
        for (int off = 1; off < 1024; off <<= 1) {
            int u = (t >= off) ? s[t - off] : 0;
            __syncthreads();
            s[t] += u;
            __syncthreads();
        }
        int out = s[t] + carry_s;
        if (i <= Nn) g_deg[i] = out;
        __syncthreads();
        if (t == 1023) carry_s = out;
        __syncthreads();
    }
}

__global__ void k_fill(const int* __restrict__ ei, const int* __restrict__ et) {
    int e = blockIdx.x * blockDim.x + threadIdx.x;
    if (e >= Ee) return;
    int dst = ei[Ee + e];
    int pos = g_deg[dst] + atomicAdd(&g_cursor[dst], 1);
    g_epack[pos] = make_int2(ei[e], et[e]);
}

// ---------------- x init ----------------
__global__ void k_init(const float* __restrict__ be, const float* __restrict__ rel,
                       const int* __restrict__ h_index, const int* __restrict__ r_index) {
    int idx = blockIdx.x * blockDim.x + threadIdx.x;
    if (idx >= Bb * Nn * Dd) return;
    int d = idx & (Dd - 1);
    int bn = idx >> 6;
    int b = bn / Nn;
    int n = bn - b * Nn;
    float v = be[idx];
    if (n == h_index[b]) v += rel[(b * Rr + r_index[b]) * Dd + d];
    g_x[idx] = v;
}

// ---------------- gather aggregation (atomic-free) ----------------
// one warp per (b, node): agg[row] = boundary[row] + sum_edges x[src]*rel[et]
__global__ void k_gather(const float* __restrict__ be, const float* __restrict__ rel,
                         const int* __restrict__ h_index, const int* __restrict__ r_index) {
    int wid = blockIdx.x * 8 + (threadIdx.x >> 5);
    int lane = threadIdx.x & 31;
    if (wid >= Bb * Nn) return;
    int b = (wid >= Nn) ? 1 : 0;
    int n = wid - b * Nn;

    float2 acc = *reinterpret_cast<const float2*>(&be[((size_t)wid << 6) + 2 * lane]);
    if (n == h_index[b]) {
        float2 q = *reinterpret_cast<const float2*>(&rel[((b * Rr + r_index[b]) << 6) + 2 * lane]);
        acc.x += q.x; acc.y += q.y;
    }

    int s = g_deg[n], e = g_deg[n + 1];
    int k = s;
    // unroll-2 for MLP
    for (; k + 1 < e; k += 2) {
        int2 e0 = g_epack[k];
        int2 e1 = g_epack[k + 1];
        float2 x0 = *reinterpret_cast<const float2*>(&g_x[((b * Nn + e0.x) << 6) + 2 * lane]);
        float2 r0 = *reinterpret_cast<const float2*>(&rel[((b * Rr + e0.y) << 6) + 2 * lane]);
        float2 x1 = *reinterpret_cast<const float2*>(&g_x[((b * Nn + e1.x) << 6) + 2 * lane]);
        float2 r1 = *reinterpret_cast<const float2*>(&rel[((b * Rr + e1.y) << 6) + 2 * lane]);
        acc.x += x0.x * r0.x; acc.y += x0.y * r0.y;
        acc.x += x1.x * r1.x; acc.y += x1.y * r1.y;
    }
    if (k < e) {
        int2 e0 = g_epack[k];
        float2 x0 = *reinterpret_cast<const float2*>(&g_x[((b * Nn + e0.x) << 6) + 2 * lane]);
        float2 r0 = *reinterpret_cast<const float2*>(&rel[((b * Rr + e0.y) << 6) + 2 * lane]);
        acc.x += x0.x * r0.x; acc.y += x0.y * r0.y;
    }
    *reinterpret_cast<float2*>(&g_agg[((size_t)wid << 6) + 2 * lane]) = acc;
}

// ---------------- dense layer: out = relu(LN(concat(x,agg)@W + b)) + x ----------------
// 64 rows/block, 8 rows per warp; lane owns outputs {lane, lane+32}.
// W stored TRANSPOSED in smem: sWt[d][j], 128 floats per d-row, XOR-swizzled in
// 16B chunks (chunk c stored at c ^ (d&31)) -> lane-indexed LDS.128 is conflict-free.
// Accumulators are packed f32x2 over (even j, odd j); broadcast input float2 is
// the packed multiplicand directly (fma.rn.f32x2, no packing MOVs).
__global__ void k_dense(const float* __restrict__ W, const float* __restrict__ bias,
                        const float* __restrict__ gam, const float* __restrict__ bet) {
    extern __shared__ float smem[];
    float* sWt = smem;               // 64 * 128 floats, swizzled   (32 KB)
    float* sIn = smem + 64 * 128;    // 64 rows * 128 floats        (32 KB)

    const int tid  = threadIdx.x;
    const int w    = tid >> 5;
    const int lane = tid & 31;
    const int base = blockIdx.x * 64;

    // transpose + swizzle W: global W[j][d] -> sWt[d*128 + ((j>>2 ^ d)<<2) + (j&3)]
    #pragma unroll
    for (int k = 0; k < 32; k++) {
        int idx = k * 256 + tid;
        int j = idx >> 6;
        int d = idx & 63;
        sWt[d * 128 + (((j >> 2) ^ (d & 31)) << 2) + (j & 3)] = W[idx];
    }
    // load inputs: row r, cols 0..63 = x, 64..127 = agg
    {
        float4* sInv = reinterpret_cast<float4*>(sIn);
        #pragma unroll
        for (int k = 0; k < 8; k++) {
            int pos = k * 256 + tid;
            int r   = pos >> 5;
            int c4  = pos & 31;
            int row = base + r;
            float4 v = make_float4(0.f, 0.f, 0.f, 0.f);
            if (row < Bb * Nn) {
                if (c4 < 16)
                    v = *reinterpret_cast<const float4*>(&g_x[((size_t)row << 6) + (c4 << 2)]);
                else
                    v = *reinterpret_cast<const float4*>(&g_agg[((size_t)row << 6) + ((c4 - 16) << 2)]);
            }
            sInv[pos] = v;
        }
    }
    __syncthreads();

    const int r0 = w * 8;
    unsigned long long acc0[8], acc1[8];
    #pragma unroll
    for (int i = 0; i < 8; i++) { acc0[i] = 0ULL; acc1[i] = 0ULL; }

    const float* wb0 = sWt + lane * 128;
    const float* wb1 = sWt + (lane + 32) * 128;

    #pragma unroll 4
    for (int j4 = 0; j4 < 32; j4++) {
        int off = (j4 ^ lane) << 2;
        ulonglong2 wa = *reinterpret_cast<const ulonglong2*>(wb0 + off);
        ulonglong2 wbv = *reinterpret_cast<const ulonglong2*>(wb1 + off);
        #pragma unroll
        for (int i = 0; i < 8; i++) {
            ulonglong2 in = *reinterpret_cast<const ulonglong2*>(&sIn[(r0 + i) * 128 + (j4 << 2)]);
            FMA2(acc0[i], in.x, wa.x, acc0[i]);
            FMA2(acc0[i], in.y, wa.y, acc0[i]);
            FMA2(acc1[i], in.x, wbv.x, acc1[i]);
            FMA2(acc1[i], in.y, wbv.y, acc1[i]);
        }
    }

    float bx = bias[lane], by = bias[lane + 32];
    float gx = gam[lane],  gy = gam[lane + 32];
    float tx = bet[lane],  ty = bet[lane + 32];

    #pragma unroll
    for (int i = 0; i < 8; i++) {
        int row = base + r0 + i;
        if (row >= Bb * Nn) break;   // uniform across warp
        float2 a0, a1;
        asm("mov.b64 {%0,%1}, %2;" : "=f"(a0.x), "=f"(a0.y) : "l"(acc0[i]));
        asm("mov.b64 {%0,%1}, %2;" : "=f"(a1.x), "=f"(a1.y) : "l"(acc1[i]));
        float o0 = a0.x + a0.y + bx;
        float o1 = a1.x + a1.y + by;

        float s = o0 + o1;
        #pragma unroll
        for (int o = 16; o > 0; o >>= 1) s += __shfl_xor_sync(0xffffffffu, s, o);
        float mu = s * (1.0f / 64.0f);
        float c0 = o0 - mu, c1 = o1 - mu;
        float q = c0 * c0 + c1 * c1;
        #pragma unroll
        for (int o = 16; o > 0; o >>= 1) q += __shfl_xor_sync(0xffffffffu, q, o);
        float inv = rsqrtf(q * (1.0f / 64.0f) + 1e-5f);

        float x0 = sIn[(r0 + i) * 128 + lane];
        float x1 = sIn[(r0 + i) * 128 + lane + 32];
        g_x[((size_t)row << 6) + lane]      = fmaxf(c0 * inv * gx + tx, 0.0f) + x0;
        g_x[((size_t)row << 6) + lane + 32] = fmaxf(c1 * inv * gy + ty, 0.0f) + x1;
    }
}

// ---------------- output MLP ----------------
__global__ void k_out(const int* __restrict__ t_index, const int* __restrict__ r_index,
                      const float* __restrict__ rel,
                      const float* __restrict__ w1, const float* __restrict__ b1,
                      const float* __restrict__ w2, const float* __restrict__ b2,
                      float* __restrict__ out) {
    __shared__ float feat[2 * Dd];
    __shared__ float red[64];
    int b = blockIdx.x >> 5;   // Kk == 32
    int k = blockIdx.x & 31;
    int tid = threadIdx.x;     // 0..63
    int t = t_index[b * Kk + k];
    feat[tid]      = g_x[((size_t)(b * Nn + t)) * Dd + tid];
    feat[Dd + tid] = rel[(b * Rr + r_index[b]) * Dd + tid];
    __syncthreads();
    float h = b1[tid];
    #pragma unroll
    for (int j = 0; j < 2 * Dd; j++) h += feat[j] * w1[j * Dd + tid];
    h = fmaxf(h, 0.0f);
    red[tid] = h * w2[tid];
    __syncthreads();
    if (tid < 32) {
        float v = red[tid] + red[tid + 32];
        #pragma unroll
        for (int o = 16; o > 0; o >>= 1) v += __shfl_xor_sync(0xffffffffu, v, o);
        if (tid == 0) out[blockIdx.x] = v + b2[0];
    }
}

extern "C" void kernel_launch(void* const* d_in, const int* in_sizes, int n_in,
                              void* d_out, int out_size) {
    const int*   edge_index = (const int*)d_in[0];
    const int*   edge_type  = (const int*)d_in[1];
    const int*   h_index    = (const int*)d_in[2];
    const int*   r_index    = (const int*)d_in[3];
    const int*   t_index    = (const int*)d_in[4];
    const float* rel        = (const float*)d_in[5];
    const float* be         = (const float*)d_in[6];
    const float* lW         = (const float*)d_in[7];
    const float* lb         = (const float*)d_in[8];
    const float* lng        = (const float*)d_in[9];
    const float* lnb        = (const float*)d_in[10];
    const float* w1         = (const float*)d_in[11];
    const float* b1         = (const float*)d_in[12];
    const float* w2         = (const float*)d_in[13];
    const float* b2         = (const float*)d_in[14];
    float* out = (float*)d_out;

    const int bnd = Bb * Nn * Dd;
    const int init_blocks  = (bnd + 255) / 256;
    const int edge_blocks  = (Ee + 255) / 256;
    const int node_blocks  = (Nn + 1 + 255) / 256;
    const int gather_blocks = (Bb * Nn + 7) / 8;    // 12500 (8 warps/block)
    const int dense_blocks  = (Bb * Nn + 63) / 64;  // 1563
    const int dense_smem    = 2 * 64 * 128 * sizeof(float);  // 64 KB

    static int attr_set = 0;
    if (!attr_set) {
        cudaFuncSetAttribute(k_dense, cudaFuncAttributeMaxDynamicSharedMemorySize, dense_smem);
        attr_set = 1;
    }

    // CSR build (per launch; edges are identical across layers)
    k_zero<<<node_blocks, 256>>>();
    k_hist<<<edge_blocks, 256>>>(edge_index);
    k_scan<<<1, 1024>>>();
    k_fill<<<edge_blocks, 256>>>(edge_index, edge_type);

    // x = boundary
    k_init<<<init_blocks, 256>>>(be, rel, h_index, r_index);

    for (int l = 0; l < Ll; l++) {
        k_gather<<<gather_blocks, 256>>>(be, rel, h_index, r_index);
        k_dense<<<dense_blocks, 256, dense_smem>>>(lW + l * 2 * Dd * Dd, lb + l * Dd,
                                                   lng + l * Dd, lnb + l * Dd);
    }

    k_out<<<Bb * Kk, 64>>>(t_index, r_index, rel, w1, b1, w2, b2, out);
}

// round 4
// speedup vs baseline: 3.5962x; 1.0654x over previous
#include <cuda_runtime.h>
#include <math.h>

#define Nn 50000
#define Ee 800000
#define Rr 64
#define Dd 64
#define Ll 4
#define Bb 2
#define Kk 32

// scratch (no allocations allowed)
__device__ float g_x[Bb * Nn * Dd];    // 25.6 MB
__device__ float g_agg[Bb * Nn * Dd];  // 25.6 MB
__device__ int   g_deg[Nn + 1];        // histogram -> rowptr (in place)
__device__ int   g_cursor[Nn];         // rowptr copy, consumed by k_fill
__device__ int2  g_epack[Ee];          // (src, edge_type) sorted by dst

#define FMA2(d, a, b, c) asm("fma.rn.f32x2 %0, %1, %2, %3;" : "=l"(d) : "l"(a), "l"(b), "l"(c))

// ---------------- CSR build ----------------
__global__ void k_zero() {
    int i = blockIdx.x * blockDim.x + threadIdx.x;
    if (i <= Nn) g_deg[i] = 0;
}

__global__ void k_hist(const int* __restrict__ ei) {
    int e = blockIdx.x * blockDim.x + threadIdx.x;
    if (e < Ee) atomicAdd(&g_deg[ei[Ee + e] + 1], 1);
}

// single-block inclusive scan over g_deg[0..Nn]; also seeds g_cursor with rowptr
__global__ void k_scan() {
    __shared__ int wsum[32];
    __shared__ int carry_s;
    int t = threadIdx.x, lane = t & 31, w = t >> 5;
    if (t == 0) carry_s = 0;
    __syncthreads();
    for (int base = 0; base <= Nn; base += 1024) {
        int i = base + t;
        int v = (i <= Nn) ? g_deg[i] : 0;
        int x = v;
        #pragma unroll
        for (int off = 1; off < 32; off <<= 1) {
            int u = __shfl_up_sync(0xffffffffu, x, off);
            if (lane >= off) x += u;
        }
        if (lane == 31) wsum[w] = x;
        __syncthreads();
        if (w == 0) {
            int y = wsum[lane];
            #pragma unroll
            for (int off = 1; off < 32; off <<= 1) {
                int u = __shfl_up_sync(0xffffffffu, y, off);
                if (lane >= off) y += u;
            }
            wsum[lane] = y;
        }
        __syncthreads();
        int out = x + ((w > 0) ? wsum[w - 1] : 0) + carry_s;
        if (i <= Nn) {
            g_deg[i] = out;
            if (i < Nn) g_cursor[i] = out;   // rowptr start for node i
        }
        __syncthreads();
        if (t == 1023) carry_s = out;
        __syncthreads();
    }
}

__global__ void k_fill(const int* __restrict__ ei, const int* __restrict__ et) {
    int e = blockIdx.x * blockDim.x + threadIdx.x;
    if (e >= Ee) return;
    int dst = ei[Ee + e];
    int pos = atomicAdd(&g_cursor[dst], 1);
    g_epack[pos] = make_int2(ei[e], et[e]);
}

// ---------------- x init ----------------
__global__ void k_init(const float* __restrict__ be, const float* __restrict__ rel,
                       const int* __restrict__ h_index, const int* __restrict__ r_index) {
    int idx = blockIdx.x * blockDim.x + threadIdx.x;
    if (idx >= Bb * Nn * Dd) return;
    int d = idx & (Dd - 1);
    int bn = idx >> 6;
    int b = bn / Nn;
    int n = bn - b * Nn;
    float v = be[idx];
    if (n == h_index[b]) v += rel[(b * Rr + r_index[b]) * Dd + d];
    g_x[idx] = v;
}

// ---------------- gather aggregation (atomic-free) ----------------
// one warp per node, BOTH batches: half-warp = batch, lane owns a float4.
// agg[b,n] = boundary[b,n] + sum_{edges dst=n} x[b,src]*rel[b,et]
__global__ void k_gather(const float* __restrict__ be, const float* __restrict__ rel,
                         const int* __restrict__ h_index, const int* __restrict__ r_index) {
    int n = blockIdx.x * 8 + (threadIdx.x >> 5);
    if (n >= Nn) return;
    int lane = threadIdx.x & 31;
    int b = lane >> 4;           // batch for this half-warp
    int c = (lane & 15) << 2;    // float4 column offset within D=64

    const size_t row = ((size_t)(b * Nn + n) << 6) + c;
    float4 acc = *reinterpret_cast<const float4*>(&be[row]);
    if (n == h_index[b]) {
        float4 q = __ldg(reinterpret_cast<const float4*>(&rel[((b * Rr + r_index[b]) << 6) + c]));
        acc.x += q.x; acc.y += q.y; acc.z += q.z; acc.w += q.w;
    }

    const int base_x = (b * Nn) << 6;
    const int base_r = (b * Rr) << 6;
    int s = g_deg[n], e = g_deg[n + 1];
    int k = s;

    #define EDGE_LOAD(ek, xv, rv)                                                        \
        float4 xv = __ldg(reinterpret_cast<const float4*>(&g_x[base_x + (ek.x << 6) + c])); \
        float4 rv = __ldg(reinterpret_cast<const float4*>(&rel[base_r + (ek.y << 6) + c]));
    #define EDGE_FMA(xv, rv)                                                             \
        acc.x += xv.x * rv.x; acc.y += xv.y * rv.y;                                      \
        acc.z += xv.z * rv.z; acc.w += xv.w * rv.w;

    for (; k + 3 < e; k += 4) {
        int2 e0 = g_epack[k];
        int2 e1 = g_epack[k + 1];
        int2 e2 = g_epack[k + 2];
        int2 e3 = g_epack[k + 3];
        EDGE_LOAD(e0, x0, r0)
        EDGE_LOAD(e1, x1, r1)
        EDGE_LOAD(e2, x2, r2)
        EDGE_LOAD(e3, x3, r3)
        EDGE_FMA(x0, r0)
        EDGE_FMA(x1, r1)
        EDGE_FMA(x2, r2)
        EDGE_FMA(x3, r3)
    }
    for (; k < e; k++) {
        int2 e0 = g_epack[k];
        EDGE_LOAD(e0, x0, r0)
        EDGE_FMA(x0, r0)
    }
    #undef EDGE_LOAD
    #undef EDGE_FMA

    *reinterpret_cast<float4*>(&g_agg[row]) = acc;
}

// ---------------- dense layer: out = relu(LN(concat(x,agg)@W + b)) + x ----------------
// 64 rows/block, 8 rows per warp; lane owns outputs {lane, lane+32}.
// W stored TRANSPOSED in smem, XOR-swizzled 16B chunks -> conflict-free LDS.128.
// Accumulators packed f32x2 (even j, odd j) via fma.rn.f32x2.
__global__ void k_dense(const float* __restrict__ W, const float* __restrict__ bias,
                        const float* __restrict__ gam, const float* __restrict__ bet) {
    extern __shared__ float smem[];
    float* sWt = smem;               // 64 * 128 floats, swizzled   (32 KB)
    float* sIn = smem + 64 * 128;    // 64 rows * 128 floats        (32 KB)

    const int tid  = threadIdx.x;
    const int w    = tid >> 5;
    const int lane = tid & 31;
    const int base = blockIdx.x * 64;

    #pragma unroll
    for (int k = 0; k < 32; k++) {
        int idx = k * 256 + tid;
        int j = idx >> 6;
        int d = idx & 63;
        sWt[d * 128 + (((j >> 2) ^ (d & 31)) << 2) + (j & 3)] = W[idx];
    }
    {
        float4* sInv = reinterpret_cast<float4*>(sIn);
        #pragma unroll
        for (int k = 0; k < 8; k++) {
            int pos = k * 256 + tid;
            int r   = pos >> 5;
            int c4  = pos & 31;
            int row = base + r;
            float4 v = make_float4(0.f, 0.f, 0.f, 0.f);
            if (row < Bb * Nn) {
                if (c4 < 16)
                    v = *reinterpret_cast<const float4*>(&g_x[((size_t)row << 6) + (c4 << 2)]);
                else
                    v = *reinterpret_cast<const float4*>(&g_agg[((size_t)row << 6) + ((c4 - 16) << 2)]);
            }
            sInv[pos] = v;
        }
    }
    __syncthreads();

    const int r0 = w * 8;
    unsigned long long acc0[8], acc1[8];
    #pragma unroll
    for (int i = 0; i < 8; i++) { acc0[i] = 0ULL; acc1[i] = 0ULL; }

    const float* wb0 = sWt + lane * 128;
    const float* wb1 = sWt + (lane + 32) * 128;

    #pragma unroll 4
    for (int j4 = 0; j4 < 32; j4++) {
        int off = (j4 ^ lane) << 2;
        ulonglong2 wa  = *reinterpret_cast<const ulonglong2*>(wb0 + off);
        ulonglong2 wbv = *reinterpret_cast<const ulonglong2*>(wb1 + off);
        #pragma unroll
        for (int i = 0; i < 8; i++) {
            ulonglong2 in = *reinterpret_cast<const ulonglong2*>(&sIn[(r0 + i) * 128 + (j4 << 2)]);
            FMA2(acc0[i], in.x, wa.x, acc0[i]);
            FMA2(acc0[i], in.y, wa.y, acc0[i]);
            FMA2(acc1[i], in.x, wbv.x, acc1[i]);
            FMA2(acc1[i], in.y, wbv.y, acc1[i]);
        }
    }

    float bx = bias[lane], by = bias[lane + 32];
    float gx = gam[lane],  gy = gam[lane + 32];
    float tx = bet[lane],  ty = bet[lane + 32];

    #pragma unroll
    for (int i = 0; i < 8; i++) {
        int row = base + r0 + i;
        if (row >= Bb * Nn) break;   // uniform across warp
        float2 a0, a1;
        asm("mov.b64 {%0,%1}, %2;" : "=f"(a0.x), "=f"(a0.y) : "l"(acc0[i]));
        asm("mov.b64 {%0,%1}, %2;" : "=f"(a1.x), "=f"(a1.y) : "l"(acc1[i]));
        float o0 = a0.x + a0.y + bx;
        float o1 = a1.x + a1.y + by;

        float s = o0 + o1;
        #pragma unroll
        for (int o = 16; o > 0; o >>= 1) s += __shfl_xor_sync(0xffffffffu, s, o);
        float mu = s * (1.0f / 64.0f);
        float c0 = o0 - mu, c1 = o1 - mu;
        float q = c0 * c0 + c1 * c1;
        #pragma unroll
        for (int o = 16; o > 0; o >>= 1) q += __shfl_xor_sync(0xffffffffu, q, o);
        float inv = rsqrtf(q * (1.0f / 64.0f) + 1e-5f);

        float x0 = sIn[(r0 + i) * 128 + lane];
        float x1 = sIn[(r0 + i) * 128 + lane + 32];
        g_x[((size_t)row << 6) + lane]      = fmaxf(c0 * inv * gx + tx, 0.0f) + x0;
        g_x[((size_t)row << 6) + lane + 32] = fmaxf(c1 * inv * gy + ty, 0.0f) + x1;
    }
}

// ---------------- output MLP ----------------
__global__ void k_out(const int* __restrict__ t_index, const int* __restrict__ r_index,
                      const float* __restrict__ rel,
                      const float* __restrict__ w1, const float* __restrict__ b1,
                      const float* __restrict__ w2, const float* __restrict__ b2,
                      float* __restrict__ out) {
    __shared__ float feat[2 * Dd];
    __shared__ float red[64];
    int b = blockIdx.x >> 5;   // Kk == 32
    int k = blockIdx.x & 31;
    int tid = threadIdx.x;     // 0..63
    int t = t_index[b * Kk + k];
    feat[tid]      = g_x[((size_t)(b * Nn + t)) * Dd + tid];
    feat[Dd + tid] = rel[(b * Rr + r_index[b]) * Dd + tid];
    __syncthreads();
    float h = b1[tid];
    #pragma unroll
    for (int j = 0; j < 2 * Dd; j++) h += feat[j] * w1[j * Dd + tid];
    h = fmaxf(h, 0.0f);
    red[tid] = h * w2[tid];
    __syncthreads();
    if (tid < 32) {
        float v = red[tid] + red[tid + 32];
        #pragma unroll
        for (int o = 16; o > 0; o >>= 1) v += __shfl_xor_sync(0xffffffffu, v, o);
        if (tid == 0) out[blockIdx.x] = v + b2[0];
    }
}

extern "C" void kernel_launch(void* const* d_in, const int* in_sizes, int n_in,
                              void* d_out, int out_size) {
    const int*   edge_index = (const int*)d_in[0];
    const int*   edge_type  = (const int*)d_in[1];
    const int*   h_index    = (const int*)d_in[2];
    const int*   r_index    = (const int*)d_in[3];
    const int*   t_index    = (const int*)d_in[4];
    const float* rel        = (const float*)d_in[5];
    const float* be         = (const float*)d_in[6];
    const float* lW         = (const float*)d_in[7];
    const float* lb         = (const float*)d_in[8];
    const float* lng        = (const float*)d_in[9];
    const float* lnb        = (const float*)d_in[10];
    const float* w1         = (const float*)d_in[11];
    const float* b1         = (const float*)d_in[12];
    const float* w2         = (const float*)d_in[13];
    const float* b2         = (const float*)d_in[14];
    float* out = (float*)d_out;

    const int bnd = Bb * Nn * Dd;
    const int init_blocks   = (bnd + 255) / 256;
    const int edge_blocks   = (Ee + 255) / 256;
    const int node_blocks   = (Nn + 1 + 255) / 256;
    const int gather_blocks = (Nn + 7) / 8;         // 6250 (8 warps/block, warp=node)
    const int dense_blocks  = (Bb * Nn + 63) / 64;  // 1563
    const int dense_smem    = 2 * 64 * 128 * sizeof(float);  // 64 KB

    static int attr_set = 0;
    if (!attr_set) {
        cudaFuncSetAttribute(k_dense, cudaFuncAttributeMaxDynamicSharedMemorySize, dense_smem);
        attr_set = 1;
    }

    // CSR build (per launch; edges identical across layers)
    k_zero<<<node_blocks, 256>>>();
    k_hist<<<edge_blocks, 256>>>(edge_index);
    k_scan<<<1, 1024>>>();
    k_fill<<<edge_blocks, 256>>>(edge_index, edge_type);

    // x = boundary
    k_init<<<init_blocks, 256>>>(be, rel, h_index, r_index);

    for (int l = 0; l < Ll; l++) {
        k_gather<<<gather_blocks, 256>>>(be, rel, h_index, r_index);
        k_dense<<<dense_blocks, 256, dense_smem>>>(lW + l * 2 * Dd * Dd, lb + l * Dd,
                                                   lng + l * Dd, lnb + l * Dd);
    }

    k_out<<<Bb * Kk, 64>>>(t_index, r_index, rel, w1, b1, w2, b2, out);
}

// round 5
// speedup vs baseline: 3.9686x; 1.1036x over previous
#include <cuda_runtime.h>
#include <math.h>

#define Nn 50000
#define Ee 800000
#define Rr 64
#define Dd 64
#define Ll 4
#define Bb 2
#define Kk 32

#define DEG_PAD 53248          // 13 * 4096, covers Nn+1

// scratch (no allocations allowed)
__device__ float g_x[Bb * Nn * Dd];    // 25.6 MB
__device__ float g_agg[Bb * Nn * Dd];  // 25.6 MB
__device__ int   g_deg[DEG_PAD];       // histogram -> rowptr (in place)
__device__ int   g_cursor[Nn];         // rowptr copy, consumed by fill
__device__ int2  g_epack[Ee];          // (src, edge_type) sorted by dst

#define FMA2(d, a, b, c) asm("fma.rn.f32x2 %0, %1, %2, %3;" : "=l"(d) : "l"(a), "l"(b), "l"(c))

// ---------------- CSR build ----------------
__global__ void k_zero() {
    int i = blockIdx.x * blockDim.x + threadIdx.x;
    if (i < DEG_PAD / 4) reinterpret_cast<int4*>(g_deg)[i] = make_int4(0, 0, 0, 0);
}

__global__ void k_hist(const int* __restrict__ ei) {
    int t = blockIdx.x * blockDim.x + threadIdx.x;
    if (t >= Ee / 4) return;
    int4 d4 = reinterpret_cast<const int4*>(ei + Ee)[t];
    atomicAdd(&g_deg[d4.x + 1], 1);
    atomicAdd(&g_deg[d4.y + 1], 1);
    atomicAdd(&g_deg[d4.z + 1], 1);
    atomicAdd(&g_deg[d4.w + 1], 1);
}

// single-block inclusive scan over g_deg[0..DEG_PAD), 4 elems/thread, 13 chunks.
// Also seeds g_cursor with rowptr starts.
__global__ void k_scan() {
    __shared__ int wsum[32];
    __shared__ int carry_s;
    int t = threadIdx.x, lane = t & 31, w = t >> 5;
    if (t == 0) carry_s = 0;
    __syncthreads();
    for (int base = 0; base < DEG_PAD; base += 4096) {
        int i0 = base + t * 4;
        int4 v = *reinterpret_cast<const int4*>(&g_deg[i0]);
        int s1 = v.x, s2 = s1 + v.y, s3 = s2 + v.z, s4 = s3 + v.w;
        int x = s4;
        #pragma unroll
        for (int off = 1; off < 32; off <<= 1) {
            int u = __shfl_up_sync(0xffffffffu, x, off);
            if (lane >= off) x += u;
        }
        if (lane == 31) wsum[w] = x;
        __syncthreads();
        if (w == 0) {
            int y = wsum[lane];
            #pragma unroll
            for (int off = 1; off < 32; off <<= 1) {
                int u = __shfl_up_sync(0xffffffffu, y, off);
                if (lane >= off) y += u;
            }
            wsum[lane] = y;
        }
        __syncthreads();
        int off0 = carry_s + ((w > 0) ? wsum[w - 1] : 0) + (x - s4);
        int4 o = make_int4(off0 + s1, off0 + s2, off0 + s3, off0 + s4);
        *reinterpret_cast<int4*>(&g_deg[i0]) = o;
        if (i0 + 0 < Nn) g_cursor[i0 + 0] = o.x;
        if (i0 + 1 < Nn) g_cursor[i0 + 1] = o.y;
        if (i0 + 2 < Nn) g_cursor[i0 + 2] = o.z;
        if (i0 + 3 < Nn) g_cursor[i0 + 3] = o.w;
        __syncthreads();
        if (t == 1023) carry_s = off0 + s4;
        __syncthreads();
    }
}

// fused: CSR fill (4 edges/thread) + x init (float4/thread)
__global__ void k_fillinit(const int* __restrict__ ei, const int* __restrict__ et,
                           const float* __restrict__ be, const float* __restrict__ rel,
                           const int* __restrict__ h_index, const int* __restrict__ r_index) {
    const int FILLT = Ee / 4;   // 200000
    int t = blockIdx.x * blockDim.x + threadIdx.x;
    if (t < FILLT) {
        int4 s4 = reinterpret_cast<const int4*>(ei)[t];
        int4 d4 = reinterpret_cast<const int4*>(ei + Ee)[t];
        int4 t4 = reinterpret_cast<const int4*>(et)[t];
        int p0 = atomicAdd(&g_cursor[d4.x], 1);
        int p1 = atomicAdd(&g_cursor[d4.y], 1);
        int p2 = atomicAdd(&g_cursor[d4.z], 1);
        int p3 = atomicAdd(&g_cursor[d4.w], 1);
        g_epack[p0] = make_int2(s4.x, t4.x);
        g_epack[p1] = make_int2(s4.y, t4.y);
        g_epack[p2] = make_int2(s4.z, t4.z);
        g_epack[p3] = make_int2(s4.w, t4.w);
    } else {
        int idx = t - FILLT;
        if (idx >= Bb * Nn * 16) return;
        int d4i = idx & 15;
        int bn = idx >> 4;
        int b = (bn >= Nn) ? 1 : 0;
        int n = bn - b * Nn;
        float4 v = reinterpret_cast<const float4*>(be)[idx];
        if (n == h_index[b]) {
            float4 q = reinterpret_cast<const float4*>(rel)[((b * Rr + r_index[b]) << 4) + d4i];
            v.x += q.x; v.y += q.y; v.z += q.z; v.w += q.w;
        }
        reinterpret_cast<float4*>(g_x)[idx] = v;
    }
}

// ---------------- gather aggregation (atomic-free) ----------------
// one warp per node, BOTH batches: half-warp = batch, lane owns a float4.
// Software-pipelined: next quad's epack entries prefetched while current
// quad's feature loads are in flight.
__global__ __launch_bounds__(256) void k_gather(const float* __restrict__ be,
                                                const float* __restrict__ rel,
                                                const int* __restrict__ h_index,
                                                const int* __restrict__ r_index) {
    int n = blockIdx.x * 8 + (threadIdx.x >> 5);
    if (n >= Nn) return;
    int lane = threadIdx.x & 31;
    int b = lane >> 4;           // batch for this half-warp
    int c = (lane & 15) << 2;    // float4 column offset within D=64

    const size_t row = ((size_t)(b * Nn + n) << 6) + c;
    float4 acc = *reinterpret_cast<const float4*>(&be[row]);
    if (n == h_index[b]) {
        float4 q = __ldg(reinterpret_cast<const float4*>(&rel[((b * Rr + r_index[b]) << 6) + c]));
        acc.x += q.x; acc.y += q.y; acc.z += q.z; acc.w += q.w;
    }

    const int base_x = (b * Nn) << 6;
    const int base_r = (b * Rr) << 6;
    int s = g_deg[n], e = g_deg[n + 1];
    int k = s;

    #define EDGE_LOAD(ek, xv, rv)                                                          \
        float4 xv = __ldg(reinterpret_cast<const float4*>(&g_x[base_x + (ek.x << 6) + c])); \
        float4 rv = __ldg(reinterpret_cast<const float4*>(&rel[base_r + (ek.y << 6) + c]));
    #define EDGE_FMA(xv, rv)                                                               \
        acc.x += xv.x * rv.x; acc.y += xv.y * rv.y;                                        \
        acc.z += xv.z * rv.z; acc.w += xv.w * rv.w;

    if (k + 3 < e) {
        int2 E0 = g_epack[k];
        int2 E1 = g_epack[k + 1];
        int2 E2 = g_epack[k + 2];
        int2 E3 = g_epack[k + 3];
        while (k + 3 < e) {
            int nk = k + 4;
            int p0 = nk     < e ? nk     : e - 1;
            int p1 = nk + 1 < e ? nk + 1 : e - 1;
            int p2 = nk + 2 < e ? nk + 2 : e - 1;
            int p3 = nk + 3 < e ? nk + 3 : e - 1;
            int2 F0 = g_epack[p0];
            int2 F1 = g_epack[p1];
            int2 F2 = g_epack[p2];
            int2 F3 = g_epack[p3];
            EDGE_LOAD(E0, x0, r0)
            EDGE_LOAD(E1, x1, r1)
            EDGE_LOAD(E2, x2, r2)
            EDGE_LOAD(E3, x3, r3)
            EDGE_FMA(x0, r0)
            EDGE_FMA(x1, r1)
            EDGE_FMA(x2, r2)
            EDGE_FMA(x3, r3)
            E0 = F0; E1 = F1; E2 = F2; E3 = F3;
            k = nk;
        }
    }
    for (; k < e; k++) {
        int2 e0 = g_epack[k];
        EDGE_LOAD(e0, x0, r0)
        EDGE_FMA(x0, r0)
    }
    #undef EDGE_LOAD
    #undef EDGE_FMA

    *reinterpret_cast<float4*>(&g_agg[row]) = acc;
}

// ---------------- dense layer: out = relu(LN(concat(x,agg)@W + b)) + x ----------------
// 64 rows/block, 8 rows per warp; lane owns outputs {lane, lane+32}.
// W stored TRANSPOSED in smem, XOR-swizzled 16B chunks -> conflict-free LDS.128.
// Accumulators packed f32x2 (even j, odd j) via fma.rn.f32x2.
__global__ void k_dense(const float* __restrict__ W, const float* __restrict__ bias,
                        const float* __restrict__ gam, const float* __restrict__ bet) {
    extern __shared__ float smem[];
    float* sWt = smem;               // 64 * 128 floats, swizzled   (32 KB)
    float* sIn = smem + 64 * 128;    // 64 rows * 128 floats        (32 KB)

    const int tid  = threadIdx.x;
    const int w    = tid >> 5;
    const int lane = tid & 31;
    const int base = blockIdx.x * 64;

    #pragma unroll
    for (int k = 0; k < 32; k++) {
        int idx = k * 256 + tid;
        int j = idx >> 6;
        int d = idx & 63;
        sWt[d * 128 + (((j >> 2) ^ (d & 31)) << 2) + (j & 3)] = W[idx];
    }
    {
        float4* sInv = reinterpret_cast<float4*>(sIn);
        #pragma unroll
        for (int k = 0; k < 8; k++) {
            int pos = k * 256 + tid;
            int r   = pos >> 5;
            int c4  = pos & 31;
            int row = base + r;
            float4 v = make_float4(0.f, 0.f, 0.f, 0.f);
            if (row < Bb * Nn) {
                if (c4 < 16)
                    v = *reinterpret_cast<const float4*>(&g_x[((size_t)row << 6) + (c4 << 2)]);
                else
                    v = *reinterpret_cast<const float4*>(&g_agg[((size_t)row << 6) + ((c4 - 16) << 2)]);
            }
            sInv[pos] = v;
        }
    }
    __syncthreads();

    const int r0 = w * 8;
    unsigned long long acc0[8], acc1[8];
    #pragma unroll
    for (int i = 0; i < 8; i++) { acc0[i] = 0ULL; acc1[i] = 0ULL; }

    const float* wb0 = sWt + lane * 128;
    const float* wb1 = sWt + (lane + 32) * 128;

    #pragma unroll 4
    for (int j4 = 0; j4 < 32; j4++) {
        int off = (j4 ^ lane) << 2;
        ulonglong2 wa  = *reinterpret_cast<const ulonglong2*>(wb0 + off);
        ulonglong2 wbv = *reinterpret_cast<const ulonglong2*>(wb1 + off);
        #pragma unroll
        for (int i = 0; i < 8; i++) {
            ulonglong2 in = *reinterpret_cast<const ulonglong2*>(&sIn[(r0 + i) * 128 + (j4 << 2)]);
            FMA2(acc0[i], in.x, wa.x, acc0[i]);
            FMA2(acc0[i], in.y, wa.y, acc0[i]);
            FMA2(acc1[i], in.x, wbv.x, acc1[i]);
            FMA2(acc1[i], in.y, wbv.y, acc1[i]);
        }
    }

    float bx = bias[lane], by = bias[lane + 32];
    float gx = gam[lane],  gy = gam[lane + 32];
    float tx = bet[lane],  ty = bet[lane + 32];

    #pragma unroll
    for (int i = 0; i < 8; i++) {
        int row = base + r0 + i;
        if (row >= Bb * Nn) break;   // uniform across warp
        float2 a0, a1;
        asm("mov.b64 {%0,%1}, %2;" : "=f"(a0.x), "=f"(a0.y) : "l"(acc0[i]));
        asm("mov.b64 {%0,%1}, %2;" : "=f"(a1.x), "=f"(a1.y) : "l"(acc1[i]));
        float o0 = a0.x + a0.y + bx;
        float o1 = a1.x + a1.y + by;

        float s = o0 + o1;
        #pragma unroll
        for (int o = 16; o > 0; o >>= 1) s += __shfl_xor_sync(0xffffffffu, s, o);
        float mu = s * (1.0f / 64.0f);
        float c0 = o0 - mu, c1 = o1 - mu;
        float q = c0 * c0 + c1 * c1;
        #pragma unroll
        for (int o = 16; o > 0; o >>= 1) q += __shfl_xor_sync(0xffffffffu, q, o);
        float inv = rsqrtf(q * (1.0f / 64.0f) + 1e-5f);

        float x0 = sIn[(r0 + i) * 128 + lane];
        float x1 = sIn[(r0 + i) * 128 + lane + 32];
        g_x[((size_t)row << 6) + lane]      = fmaxf(c0 * inv * gx + tx, 0.0f) + x0;
        g_x[((size_t)row << 6) + lane + 32] = fmaxf(c1 * inv * gy + ty, 0.0f) + x1;
    }
}

// ---------------- output MLP ----------------
__global__ void k_out(const int* __restrict__ t_index, const int* __restrict__ r_index,
                      const float* __restrict__ rel,
                      const float* __restrict__ w1, const float* __restrict__ b1,
                      const float* __restrict__ w2, const float* __restrict__ b2,
                      float* __restrict__ out) {
    __shared__ float feat[2 * Dd];
    __shared__ float red[64];
    int b = blockIdx.x >> 5;   // Kk == 32
    int k = blockIdx.x & 31;
    int tid = threadIdx.x;     // 0..63
    int t = t_index[b * Kk + k];
    feat[tid]      = g_x[((size_t)(b * Nn + t)) * Dd + tid];
    feat[Dd + tid] = rel[(b * Rr + r_index[b]) * Dd + tid];
    __syncthreads();
    float h = b1[tid];
    #pragma unroll
    for (int j = 0; j < 2 * Dd; j++) h += feat[j] * w1[j * Dd + tid];
    h = fmaxf(h, 0.0f);
    red[tid] = h * w2[tid];
    __syncthreads();
    if (tid < 32) {
        float v = red[tid] + red[tid + 32];
        #pragma unroll
        for (int o = 16; o > 0; o >>= 1) v += __shfl_xor_sync(0xffffffffu, v, o);
        if (tid == 0) out[blockIdx.x] = v + b2[0];
    }
}

extern "C" void kernel_launch(void* const* d_in, const int* in_sizes, int n_in,
                              void* d_out, int out_size) {
    const int*   edge_index = (const int*)d_in[0];
    const int*   edge_type  = (const int*)d_in[1];
    const int*   h_index    = (const int*)d_in[2];
    const int*   r_index    = (const int*)d_in[3];
    const int*   t_index    = (const int*)d_in[4];
    const float* rel        = (const float*)d_in[5];
    const float* be         = (const float*)d_in[6];
    const float* lW         = (const float*)d_in[7];
    const float* lb         = (const float*)d_in[8];
    const float* lng        = (const float*)d_in[9];
    const float* lnb        = (const float*)d_in[10];
    const float* w1         = (const float*)d_in[11];
    const float* b1         = (const float*)d_in[12];
    const float* w2         = (const float*)d_in[13];
    const float* b2         = (const float*)d_in[14];
    float* out = (float*)d_out;

    const int zero_blocks   = (DEG_PAD / 4 + 255) / 256;          // 52
    const int hist_blocks   = (Ee / 4 + 255) / 256;               // 782
    const int fi_threads    = Ee / 4 + Bb * Nn * 16;              // 1.8M
    const int fi_blocks     = (fi_threads + 255) / 256;           // 7032
    const int gather_blocks = (Nn + 7) / 8;                       // 6250
    const int dense_blocks  = (Bb * Nn + 63) / 64;                // 1563
    const int dense_smem    = 2 * 64 * 128 * sizeof(float);       // 64 KB

    static int attr_set = 0;
    if (!attr_set) {
        cudaFuncSetAttribute(k_dense, cudaFuncAttributeMaxDynamicSharedMemorySize, dense_smem);
        attr_set = 1;
    }

    // CSR build + x init (per launch; deterministic inputs)
    k_zero<<<zero_blocks, 256>>>();
    k_hist<<<hist_blocks, 256>>>(edge_index);
    k_scan<<<1, 1024>>>();
    k_fillinit<<<fi_blocks, 256>>>(edge_index, edge_type, be, rel, h_index, r_index);

    for (int l = 0; l < Ll; l++) {
        k_gather<<<gather_blocks, 256>>>(be, rel, h_index, r_index);
        k_dense<<<dense_blocks, 256, dense_smem>>>(lW + l * 2 * Dd * Dd, lb + l * Dd,
                                                   lng + l * Dd, lnb + l * Dd);
    }

    k_out<<<Bb * Kk, 64>>>(t_index, r_index, rel, w1, b1, w2, b2, out);
}